// round 5
// baseline (speedup 1.0000x reference)
#include <cuda_runtime.h>
#include <cuda_bf16.h>
#include <stdint.h>

// Problem constants: N=100000, E=1600000, IN=128, H=OUT=64
#define NMAX 100000
#define EMAX 1600000
#define HF   64

// Scratch (allocation-free device globals; zero-initialized at module load,
// and every kernel that dirties a cross-replay buffer re-zeros it at the end
// of the replay so the CUDA-graph replay invariant holds).
__device__ float  g_hs [(size_t)NMAX * HF];
__device__ float  g_acc[(size_t)NMAX * HF];
__device__ float  g_dinv[NMAX];
__device__ int    g_deg [NMAX];
__device__ int    g_off [NMAX + 1];
__device__ int    g_cursor[NMAX];
__device__ int    g_adj [EMAX];
__device__ double g_sums[2 * HF];
__device__ float  g_scale[HF];
__device__ float  g_shift[HF];
__device__ int    g_ticket;

// ---------------------------------------------------------------------------
// MMA helpers (HMMA bf16 — plain sm_80+ PTX)
// ---------------------------------------------------------------------------
__device__ __forceinline__ uint32_t smem_u32(const void* p) {
    uint32_t a;
    asm("{ .reg .u64 t; cvta.to.shared.u64 t, %1; cvt.u32.u64 %0, t; }"
        : "=r"(a) : "l"(p));
    return a;
}

__device__ __forceinline__ void ldsm_x4(uint32_t* r, uint32_t addr) {
    asm volatile("ldmatrix.sync.aligned.m8n8.x4.shared.b16 {%0,%1,%2,%3}, [%4];"
                 : "=r"(r[0]), "=r"(r[1]), "=r"(r[2]), "=r"(r[3]) : "r"(addr));
}

__device__ __forceinline__ void ldsm_x2(uint32_t* r, uint32_t addr) {
    asm volatile("ldmatrix.sync.aligned.m8n8.x2.shared.b16 {%0,%1}, [%2];"
                 : "=r"(r[0]), "=r"(r[1]) : "r"(addr));
}

__device__ __forceinline__ void mma_bf16(float* c, const uint32_t* a, const uint32_t* b) {
    asm volatile("mma.sync.aligned.m16n8k16.row.col.f32.bf16.bf16.f32 "
                 "{%0,%1,%2,%3}, {%4,%5,%6,%7}, {%8,%9}, {%0,%1,%2,%3};"
                 : "+f"(c[0]), "+f"(c[1]), "+f"(c[2]), "+f"(c[3])
                 : "r"(a[0]), "r"(a[1]), "r"(a[2]), "r"(a[3]),
                   "r"(b[0]), "r"(b[1]));
}

__device__ __forceinline__ uint32_t pack_bf2(__nv_bfloat16 lo, __nv_bfloat16 hi) {
    __nv_bfloat162 t(lo, hi);
    return *(uint32_t*)&t;
}

__device__ __forceinline__ uint2 split4(float4 v) {
    __nv_bfloat16 h0 = __float2bfloat16(v.x), h1 = __float2bfloat16(v.y);
    __nv_bfloat16 h2 = __float2bfloat16(v.z), h3 = __float2bfloat16(v.w);
    return make_uint2(pack_bf2(h0, h1), pack_bf2(h2, h3));
}

// ---------------------------------------------------------------------------
// CSR build
// ---------------------------------------------------------------------------
__global__ void deg_count_kernel(const int* __restrict__ dst, int E) {
    int i = blockIdx.x * blockDim.x + threadIdx.x;
    if (i < E) atomicAdd(&g_deg[dst[i]], 1);
}

// Single-block scan: per-thread segment sum -> block scan -> segment writeback.
__global__ void __launch_bounds__(1024, 1)
scan_kernel(int n, int E) {
    __shared__ int sh[1024];
    const int CH = (n + 1023) / 1024;
    int t  = threadIdx.x;
    int lo = t * CH;
    int hi = min(n, lo + CH);
    int s = 0;
    for (int i = lo; i < hi; i++) s += g_deg[i];
    sh[t] = s;
    for (int o = 1; o < 1024; o <<= 1) {
        __syncthreads();
        int u = (t >= o) ? sh[t - o] : 0;
        __syncthreads();
        sh[t] += u;
    }
    __syncthreads();
    int run = sh[t] - s;  // exclusive prefix of this segment
    for (int i = lo; i < hi; i++) {
        int d = g_deg[i];
        g_off[i]    = run;
        g_cursor[i] = run;
        g_dinv[i]   = rsqrtf((float)(d + 1));
        run += d;
    }
    if (t == 1023) g_off[n] = E;
}

__global__ void fill_adj_kernel(const int* __restrict__ src,
                                const int* __restrict__ dst, int E) {
    int i = blockIdx.x * blockDim.x + threadIdx.x;
    if (i < E) {
        int pos = atomicAdd(&g_cursor[dst[i]], 1);
        g_adj[pos] = src[i];
    }
}

// ---------------------------------------------------------------------------
// HMMA GEMM: hs[row] = (transform(in[row]) @ W) * dinv[row]
// Split-bf16 3-pass (hi*hi + hi*lo + lo*hi), fp32 accumulation.
// CTA tile 128x64, 8 warps (4x2 of 32x32 tiles), 256 threads.
// ---------------------------------------------------------------------------
template<int K, bool TRANS>
__global__ void __launch_bounds__(256, 1)
gemm_mma_kernel(const float* __restrict__ Xin,
                const float* __restrict__ W,
                const float* __restrict__ alpha,
                int n)
{
    constexpr int LDA  = K + 8;
    constexpr int A_HI = 0;
    constexpr int A_LO = 128 * LDA;
    constexpr int B_HI = 256 * LDA;
    constexpr int B_LO = 256 * LDA + 64 * LDA;

    extern __shared__ __nv_bfloat16 smem[];
    const uint32_t sb = smem_u32(smem);
    const int tid = threadIdx.x;
    const int wid = tid >> 5, lid = tid & 31;
    const int rowBase = blockIdx.x * 128;

    const float* X = TRANS ? g_acc : Xin;
    for (int i = tid; i < 128 * (K / 4); i += 256) {
        int r  = i / (K / 4);
        int k0 = (i % (K / 4)) * 4;
        float4 v = make_float4(0.f, 0.f, 0.f, 0.f);
        int row = rowBase + r;
        if (row < n) {
            v = *(const float4*)(X + (size_t)row * K + k0);
            if (TRANS) {
                float t;
                t = v.x * g_scale[k0+0] + g_shift[k0+0]; v.x = (t >= 0.f) ? t : t * alpha[k0+0];
                t = v.y * g_scale[k0+1] + g_shift[k0+1]; v.y = (t >= 0.f) ? t : t * alpha[k0+1];
                t = v.z * g_scale[k0+2] + g_shift[k0+2]; v.z = (t >= 0.f) ? t : t * alpha[k0+2];
                t = v.w * g_scale[k0+3] + g_shift[k0+3]; v.w = (t >= 0.f) ? t : t * alpha[k0+3];
            }
        }
        uint2 hi = split4(v);
        float4 res = make_float4(
            v.x - __bfloat162float(__float2bfloat16(v.x)),
            v.y - __bfloat162float(__float2bfloat16(v.y)),
            v.z - __bfloat162float(__float2bfloat16(v.z)),
            v.w - __bfloat162float(__float2bfloat16(v.w)));
        uint2 lo = split4(res);
        *(uint2*)(smem + A_HI + r * LDA + k0) = hi;
        *(uint2*)(smem + A_LO + r * LDA + k0) = lo;
    }

    for (int i = tid; i < 64 * (K / 4); i += 256) {
        int nn = i / (K / 4);
        int k0 = (i % (K / 4)) * 4;
        float4 v = make_float4(W[(size_t)(k0+0) * 64 + nn], W[(size_t)(k0+1) * 64 + nn],
                               W[(size_t)(k0+2) * 64 + nn], W[(size_t)(k0+3) * 64 + nn]);
        uint2 hi = split4(v);
        float4 res = make_float4(
            v.x - __bfloat162float(__float2bfloat16(v.x)),
            v.y - __bfloat162float(__float2bfloat16(v.y)),
            v.z - __bfloat162float(__float2bfloat16(v.z)),
            v.w - __bfloat162float(__float2bfloat16(v.w)));
        uint2 lo = split4(res);
        *(uint2*)(smem + B_HI + nn * LDA + k0) = hi;
        *(uint2*)(smem + B_LO + nn * LDA + k0) = lo;
    }
    __syncthreads();

    const int warpRow = wid & 3;
    const int warpCol = wid >> 2;

    float acc[2][4][4];
#pragma unroll
    for (int mi = 0; mi < 2; mi++)
#pragma unroll
        for (int ni = 0; ni < 4; ni++)
#pragma unroll
            for (int j = 0; j < 4; j++) acc[mi][ni][j] = 0.f;

    const int aRow  = warpRow * 32 + (lid & 15);
    const int aKoff = (lid >> 4) * 8;
    const int bRow  = warpCol * 32 + (lid & 7);
    const int bKoff = ((lid >> 3) & 1) * 8;

#pragma unroll
    for (int k0 = 0; k0 < K; k0 += 16) {
        uint32_t aHi[2][4], aLo[2][4], bHi[4][2], bLo[4][2];
#pragma unroll
        for (int mi = 0; mi < 2; mi++) {
            uint32_t base = (uint32_t)(((aRow + mi * 16) * LDA + k0 + aKoff) * 2);
            ldsm_x4(aHi[mi], sb + A_HI * 2 + base);
            ldsm_x4(aLo[mi], sb + A_LO * 2 + base);
        }
#pragma unroll
        for (int ni = 0; ni < 4; ni++) {
            uint32_t base = (uint32_t)(((bRow + ni * 8) * LDA + k0 + bKoff) * 2);
            ldsm_x2(bHi[ni], sb + B_HI * 2 + base);
            ldsm_x2(bLo[ni], sb + B_LO * 2 + base);
        }
#pragma unroll
        for (int mi = 0; mi < 2; mi++)
#pragma unroll
            for (int ni = 0; ni < 4; ni++) {
                mma_bf16(acc[mi][ni], aHi[mi], bHi[ni]);
                mma_bf16(acc[mi][ni], aHi[mi], bLo[ni]);
                mma_bf16(acc[mi][ni], aLo[mi], bHi[ni]);
            }
    }

    const int rBase = rowBase + warpRow * 32 + (lid >> 2);
    const int cBase = warpCol * 32 + (lid & 3) * 2;
#pragma unroll
    for (int mi = 0; mi < 2; mi++) {
#pragma unroll
        for (int h = 0; h < 2; h++) {
            int row = rBase + mi * 16 + h * 8;
            if (row < n) {
                float dv = g_dinv[row];
                float* o = g_hs + (size_t)row * 64;
#pragma unroll
                for (int ni = 0; ni < 4; ni++) {
                    float2 v = make_float2(acc[mi][ni][h * 2 + 0] * dv,
                                           acc[mi][ni][h * 2 + 1] * dv);
                    *(float2*)(o + cBase + ni * 8) = v;
                }
            }
        }
    }
}

// ---------------------------------------------------------------------------
// CSR gather: acc[v] = dinv[v] * (hs[v] + sum_{adj} hs[s])
// ---------------------------------------------------------------------------
__global__ void gather_kernel(int n)
{
    int idx = blockIdx.x * blockDim.x + threadIdx.x;
    int v = idx >> 4;
    int c = idx & 15;
    if (v >= n) return;
    int e0 = g_off[v];
    int e1 = g_off[v + 1];
    float4 tot = ((const float4*)g_hs)[(size_t)v * 16 + c];
    for (int e = e0; e < e1; e++) {
        int s = __ldg(&g_adj[e]);
        float4 m = ((const float4*)g_hs)[(size_t)s * 16 + c];
        tot.x += m.x; tot.y += m.y; tot.z += m.z; tot.w += m.w;
    }
    float dv = g_dinv[v];
    tot.x *= dv; tot.y *= dv; tot.z *= dv; tot.w *= dv;
    ((float4*)g_acc)[(size_t)v * 16 + c] = tot;
}

// ---------------------------------------------------------------------------
// BN stats + fused finalize (last-block ticket pattern)
// ---------------------------------------------------------------------------
__global__ void stats_fin_kernel(int n,
                                 const float* __restrict__ gam,
                                 const float* __restrict__ bet)
{
    __shared__ float sh1[256], sh2[256];
    __shared__ bool lastBlock;
    int t  = threadIdx.x;
    int f  = t & 63;
    int rg = t >> 6;
    int r0   = blockIdx.x * 256;
    int rend = min(n, r0 + 256);
    float s1 = 0.f, s2 = 0.f;
    for (int r = r0 + rg; r < rend; r += 4) {
        float v = g_acc[(size_t)r * 64 + f];
        s1 += v;
        s2 += v * v;
    }
    sh1[t] = s1; sh2[t] = s2;
    __syncthreads();
    if (t < 64) {
        float a1 = sh1[t] + sh1[t + 64] + sh1[t + 128] + sh1[t + 192];
        float a2 = sh2[t] + sh2[t + 64] + sh2[t + 128] + sh2[t + 192];
        atomicAdd(&g_sums[t],      (double)a1);
        atomicAdd(&g_sums[64 + t], (double)a2);
    }
    __threadfence();
    if (t == 0) {
        int c = atomicAdd(&g_ticket, 1);
        lastBlock = (c == (int)gridDim.x - 1);
    }
    __syncthreads();
    if (lastBlock) {
        if (t < 64) {
            double inv_n = 1.0 / (double)n;
            double sA = atomicAdd(&g_sums[t], 0.0);       // coherent L2 read
            double sB = atomicAdd(&g_sums[64 + t], 0.0);
            float mu  = (float)(sA * inv_n);
            float var = (float)(sB * inv_n) - mu * mu;
            float rs  = rsqrtf(var + 1e-5f);
            float sc  = rs * gam[t];
            g_scale[t] = sc;
            g_shift[t] = bet[t] - mu * sc;
            g_sums[t] = 0.0;            // reset for next layer / next replay
            g_sums[64 + t] = 0.0;
        }
        if (t == 0) g_ticket = 0;
    }
}

// ---------------------------------------------------------------------------
// Final output + cross-replay cleanup (re-zero g_deg for the next replay)
// ---------------------------------------------------------------------------
__global__ void out_kernel(const float* __restrict__ alpha,
                           float* __restrict__ out, int n)
{
    int idx = blockIdx.x * blockDim.x + threadIdx.x;
    if (idx < n) g_deg[idx] = 0;
    if (idx >= n * 64) return;
    int f = idx & 63;
    float v = g_acc[idx] * g_scale[f] + g_shift[f];
    out[idx] = (v >= 0.f) ? v : alpha[f] * v;
}

// ---------------------------------------------------------------------------
// Launch
// ---------------------------------------------------------------------------
extern "C" void kernel_launch(void* const* d_in, const int* in_sizes, int n_in,
                              void* d_out, int out_size)
{
    const float* x   = (const float*)d_in[0];
    const int*   ei  = (const int*)  d_in[1];
    const int N = in_sizes[0] / 128;
    const int E = in_sizes[1] / 2;
    const int* src = ei;
    const int* dst = ei + E;

    const float* W1  = (const float*)d_in[2];
    const float* G1  = (const float*)d_in[4];
    const float* BE1 = (const float*)d_in[5];
    const float* A1  = (const float*)d_in[6];
    const float* W2  = (const float*)d_in[7];
    const float* G2  = (const float*)d_in[9];
    const float* BE2 = (const float*)d_in[10];
    const float* A2  = (const float*)d_in[11];
    const float* W3  = (const float*)d_in[12];
    const float* G3  = (const float*)d_in[14];
    const float* BE3 = (const float*)d_in[15];
    const float* A3  = (const float*)d_in[16];

    const int smem128 = 384 * (128 + 8) * 2;  // 104448 B
    const int smem64  = 384 * (64 + 8) * 2;   //  55296 B
    cudaFuncSetAttribute((const void*)gemm_mma_kernel<128, false>,
                         cudaFuncAttributeMaxDynamicSharedMemorySize, smem128);
    cudaFuncSetAttribute((const void*)gemm_mma_kernel<64, true>,
                         cudaFuncAttributeMaxDynamicSharedMemorySize, smem64);

    const int gN  = (N + 255) / 256;
    const int gE  = (E + 255) / 256;
    const int gG  = (N + 127) / 128;
    const int gGa = (N * 16 + 255) / 256;
    const int gO  = (N * 64 + 255) / 256;

    // CSR build (g_deg is zero here: static init on run 1, out_kernel re-zeros after)
    deg_count_kernel<<<gE, 256>>>(dst, E);
    scan_kernel     <<<1, 1024>>>(N, E);
    fill_adj_kernel <<<gE, 256>>>(src, dst, E);

    // ---- Layer 1 ----
    gemm_mma_kernel<128, false><<<gG, 256, smem128>>>(x, W1, nullptr, N);
    gather_kernel   <<<gGa, 256>>>(N);
    stats_fin_kernel<<<gN, 256>>>(N, G1, BE1);

    // ---- Layer 2 ----
    gemm_mma_kernel<64, true><<<gG, 256, smem64>>>(nullptr, W2, A1, N);
    gather_kernel   <<<gGa, 256>>>(N);
    stats_fin_kernel<<<gN, 256>>>(N, G2, BE2);

    // ---- Layer 3 ----
    gemm_mma_kernel<64, true><<<gG, 256, smem64>>>(nullptr, W3, A2, N);
    gather_kernel   <<<gGa, 256>>>(N);
    stats_fin_kernel<<<gN, 256>>>(N, G3, BE3);

    out_kernel<<<gO, 256>>>(A3, (float*)d_out, N);
}

// round 6
// speedup vs baseline: 1.8276x; 1.8276x over previous
#include <cuda_runtime.h>
#include <cuda_bf16.h>
#include <stdint.h>

// Problem constants: N=100000, E=1600000, IN=128, H=OUT=64
#define NMAX 100000
#define EMAX 1600000
#define HF   64

// Scratch (allocation-free device globals)
__device__ float  g_hs [(size_t)NMAX * HF];
__device__ float  g_acc[(size_t)NMAX * HF];
__device__ float  g_dinv[NMAX];
__device__ int    g_deg [NMAX];
__device__ int    g_off [NMAX + 1];
__device__ int    g_cursor[NMAX];
__device__ int    g_adj [EMAX];
__device__ int    g_bsum[256];
__device__ int    g_bpre[256];
__device__ double g_sums[2 * HF];
__device__ float  g_scale[HF];
__device__ float  g_shift[HF];

// ---------------------------------------------------------------------------
// MMA helpers (HMMA bf16 — plain sm_80+ PTX)
// ---------------------------------------------------------------------------
__device__ __forceinline__ uint32_t smem_u32(const void* p) {
    uint32_t a;
    asm("{ .reg .u64 t; cvta.to.shared.u64 t, %1; cvt.u32.u64 %0, t; }"
        : "=r"(a) : "l"(p));
    return a;
}

__device__ __forceinline__ void ldsm_x4(uint32_t* r, uint32_t addr) {
    asm volatile("ldmatrix.sync.aligned.m8n8.x4.shared.b16 {%0,%1,%2,%3}, [%4];"
                 : "=r"(r[0]), "=r"(r[1]), "=r"(r[2]), "=r"(r[3]) : "r"(addr));
}

__device__ __forceinline__ void ldsm_x2(uint32_t* r, uint32_t addr) {
    asm volatile("ldmatrix.sync.aligned.m8n8.x2.shared.b16 {%0,%1}, [%2];"
                 : "=r"(r[0]), "=r"(r[1]) : "r"(addr));
}

__device__ __forceinline__ void mma_bf16(float* c, const uint32_t* a, const uint32_t* b) {
    asm volatile("mma.sync.aligned.m16n8k16.row.col.f32.bf16.bf16.f32 "
                 "{%0,%1,%2,%3}, {%4,%5,%6,%7}, {%8,%9}, {%0,%1,%2,%3};"
                 : "+f"(c[0]), "+f"(c[1]), "+f"(c[2]), "+f"(c[3])
                 : "r"(a[0]), "r"(a[1]), "r"(a[2]), "r"(a[3]),
                   "r"(b[0]), "r"(b[1]));
}

__device__ __forceinline__ uint32_t pack_bf2(__nv_bfloat16 lo, __nv_bfloat16 hi) {
    __nv_bfloat162 t(lo, hi);
    return *(uint32_t*)&t;
}

__device__ __forceinline__ uint2 split4(float4 v) {
    __nv_bfloat16 h0 = __float2bfloat16(v.x), h1 = __float2bfloat16(v.y);
    __nv_bfloat16 h2 = __float2bfloat16(v.z), h3 = __float2bfloat16(v.w);
    return make_uint2(pack_bf2(h0, h1), pack_bf2(h2, h3));
}

// ---------------------------------------------------------------------------
// Degree / CSR build (R4 structure — measured good)
// ---------------------------------------------------------------------------
__global__ void deg_init_kernel(int n) {
    int i = blockIdx.x * blockDim.x + threadIdx.x;
    if (i < n) g_deg[i] = 0;
    if (blockIdx.x == 0 && threadIdx.x < 2 * HF) g_sums[threadIdx.x] = 0.0;
}

__global__ void deg_count_kernel(const int* __restrict__ dst, int E) {
    int i = blockIdx.x * blockDim.x + threadIdx.x;
    if (i < E) atomicAdd(&g_deg[dst[i]], 1);
}

__global__ void scan_bsum_kernel(int n) {
    __shared__ int sh[256];
    int b = blockIdx.x, t = threadIdx.x;
    int base = b * 1024;
    int s = 0;
    for (int i = t; i < 1024; i += 256) {
        int idx = base + i;
        if (idx < n) s += g_deg[idx];
    }
    sh[t] = s;
    __syncthreads();
    for (int o = 128; o > 0; o >>= 1) {
        if (t < o) sh[t] += sh[t + o];
        __syncthreads();
    }
    if (t == 0) g_bsum[b] = sh[0];
}

__global__ void scan_tops_kernel(int nb, int n, int E) {
    if (threadIdx.x == 0) {
        int run = 0;
        for (int i = 0; i < nb; i++) { g_bpre[i] = run; run += g_bsum[i]; }
        g_off[n] = E;
    }
}

__global__ void scan_final_kernel(int n) {
    __shared__ int sh[1024];
    int b = blockIdx.x, t = threadIdx.x;
    int idx = b * 1024 + t;
    int v = (idx < n) ? g_deg[idx] : 0;
    sh[t] = v;
    for (int o = 1; o < 1024; o <<= 1) {
        __syncthreads();
        int u = (t >= o) ? sh[t - o] : 0;
        __syncthreads();
        sh[t] += u;
    }
    __syncthreads();
    if (idx < n) {
        int ex = sh[t] - v + g_bpre[b];
        g_off[idx]    = ex;
        g_cursor[idx] = ex;
        g_dinv[idx]   = rsqrtf((float)(v + 1));
    }
}

__global__ void fill_adj_kernel(const int* __restrict__ src,
                                const int* __restrict__ dst, int E) {
    int i = blockIdx.x * blockDim.x + threadIdx.x;
    if (i < E) {
        int pos = atomicAdd(&g_cursor[dst[i]], 1);
        g_adj[pos] = src[i];
    }
}

// ---------------------------------------------------------------------------
// HMMA GEMM: hs[row] = (transform(in[row]) @ W) * dinv[row]
// Split-bf16 3-pass (hi*hi + hi*lo + lo*hi), fp32 accumulation.
// CTA tile 128x64, 512 threads = 16 warps (8x2 grid of 16x32 warp tiles).
// ---------------------------------------------------------------------------
template<int K, bool TRANS>
__global__ void __launch_bounds__(512, 1)
gemm_mma_kernel(const float* __restrict__ Xin,
                const float* __restrict__ W,
                const float* __restrict__ alpha,
                int n)
{
    constexpr int LDA  = K + 8;
    constexpr int A_HI = 0;
    constexpr int A_LO = 128 * LDA;
    constexpr int B_HI = 256 * LDA;
    constexpr int B_LO = 256 * LDA + 64 * LDA;

    extern __shared__ __nv_bfloat16 smem[];
    const uint32_t sb = smem_u32(smem);
    const int tid = threadIdx.x;
    const int wid = tid >> 5, lid = tid & 31;
    const int rowBase = blockIdx.x * 128;

    const float* X = TRANS ? g_acc : Xin;
    for (int i = tid; i < 128 * (K / 4); i += 512) {
        int r  = i / (K / 4);
        int k0 = (i % (K / 4)) * 4;
        float4 v = make_float4(0.f, 0.f, 0.f, 0.f);
        int row = rowBase + r;
        if (row < n) {
            v = *(const float4*)(X + (size_t)row * K + k0);
            if (TRANS) {
                float t;
                t = v.x * g_scale[k0+0] + g_shift[k0+0]; v.x = (t >= 0.f) ? t : t * alpha[k0+0];
                t = v.y * g_scale[k0+1] + g_shift[k0+1]; v.y = (t >= 0.f) ? t : t * alpha[k0+1];
                t = v.z * g_scale[k0+2] + g_shift[k0+2]; v.z = (t >= 0.f) ? t : t * alpha[k0+2];
                t = v.w * g_scale[k0+3] + g_shift[k0+3]; v.w = (t >= 0.f) ? t : t * alpha[k0+3];
            }
        }
        uint2 hi = split4(v);
        float4 res = make_float4(
            v.x - __bfloat162float(__float2bfloat16(v.x)),
            v.y - __bfloat162float(__float2bfloat16(v.y)),
            v.z - __bfloat162float(__float2bfloat16(v.z)),
            v.w - __bfloat162float(__float2bfloat16(v.w)));
        uint2 lo = split4(res);
        *(uint2*)(smem + A_HI + r * LDA + k0) = hi;
        *(uint2*)(smem + A_LO + r * LDA + k0) = lo;
    }

    for (int i = tid; i < 64 * (K / 4); i += 512) {
        int nn = i / (K / 4);
        int k0 = (i % (K / 4)) * 4;
        float4 v = make_float4(W[(size_t)(k0+0) * 64 + nn], W[(size_t)(k0+1) * 64 + nn],
                               W[(size_t)(k0+2) * 64 + nn], W[(size_t)(k0+3) * 64 + nn]);
        uint2 hi = split4(v);
        float4 res = make_float4(
            v.x - __bfloat162float(__float2bfloat16(v.x)),
            v.y - __bfloat162float(__float2bfloat16(v.y)),
            v.z - __bfloat162float(__float2bfloat16(v.z)),
            v.w - __bfloat162float(__float2bfloat16(v.w)));
        uint2 lo = split4(res);
        *(uint2*)(smem + B_HI + nn * LDA + k0) = hi;
        *(uint2*)(smem + B_LO + nn * LDA + k0) = lo;
    }
    __syncthreads();

    // 16 warps: 8 row-groups (16 rows) x 2 col-groups (32 cols)
    const int warpRow = wid & 7;
    const int warpCol = wid >> 3;

    float acc[4][4];
#pragma unroll
    for (int ni = 0; ni < 4; ni++)
#pragma unroll
        for (int j = 0; j < 4; j++) acc[ni][j] = 0.f;

    const int aRow  = warpRow * 16 + (lid & 15);
    const int aKoff = (lid >> 4) * 8;
    const int bRow  = warpCol * 32 + (lid & 7);
    const int bKoff = ((lid >> 3) & 1) * 8;

#pragma unroll
    for (int k0 = 0; k0 < K; k0 += 16) {
        uint32_t aHi[4], aLo[4], bHi[4][2], bLo[4][2];
        {
            uint32_t base = (uint32_t)((aRow * LDA + k0 + aKoff) * 2);
            ldsm_x4(aHi, sb + A_HI * 2 + base);
            ldsm_x4(aLo, sb + A_LO * 2 + base);
        }
#pragma unroll
        for (int ni = 0; ni < 4; ni++) {
            uint32_t base = (uint32_t)(((bRow + ni * 8) * LDA + k0 + bKoff) * 2);
            ldsm_x2(bHi[ni], sb + B_HI * 2 + base);
            ldsm_x2(bLo[ni], sb + B_LO * 2 + base);
        }
#pragma unroll
        for (int ni = 0; ni < 4; ni++) {
            mma_bf16(acc[ni], aHi, bHi[ni]);
            mma_bf16(acc[ni], aHi, bLo[ni]);
            mma_bf16(acc[ni], aLo, bHi[ni]);
        }
    }

    // Epilogue: scale by dinv, store
    const int rBase = rowBase + warpRow * 16 + (lid >> 2);
    const int cBase = warpCol * 32 + (lid & 3) * 2;
#pragma unroll
    for (int h = 0; h < 2; h++) {
        int row = rBase + h * 8;
        if (row < n) {
            float dv = g_dinv[row];
            float* o = g_hs + (size_t)row * 64;
#pragma unroll
            for (int ni = 0; ni < 4; ni++) {
                float2 v = make_float2(acc[ni][h * 2 + 0] * dv,
                                       acc[ni][h * 2 + 1] * dv);
                *(float2*)(o + cBase + ni * 8) = v;
            }
        }
    }
}

// ---------------------------------------------------------------------------
// CSR gather: acc[v] = dinv[v] * (hs[v] + sum_{adj} hs[s])
// ---------------------------------------------------------------------------
__global__ void gather_kernel(int n)
{
    int idx = blockIdx.x * blockDim.x + threadIdx.x;
    int v = idx >> 4;
    int c = idx & 15;
    if (v >= n) return;
    int e0 = g_off[v];
    int e1 = g_off[v + 1];
    float4 tot = ((const float4*)g_hs)[(size_t)v * 16 + c];
    for (int e = e0; e < e1; e++) {
        int s = __ldg(&g_adj[e]);
        float4 m = ((const float4*)g_hs)[(size_t)s * 16 + c];
        tot.x += m.x; tot.y += m.y; tot.z += m.z; tot.w += m.w;
    }
    float dv = g_dinv[v];
    tot.x *= dv; tot.y *= dv; tot.z *= dv; tot.w *= dv;
    ((float4*)g_acc)[(size_t)v * 16 + c] = tot;
}

// ---------------------------------------------------------------------------
// BN stats / finalize / output (R4 structure — measured good)
// ---------------------------------------------------------------------------
__global__ void stats_kernel(int n)
{
    __shared__ float sh1[256], sh2[256];
    int t  = threadIdx.x;
    int f  = t & 63;
    int rg = t >> 6;
    int r0   = blockIdx.x * 256;
    int rend = min(n, r0 + 256);
    float s1 = 0.f, s2 = 0.f;
    for (int r = r0 + rg; r < rend; r += 4) {
        float v = g_acc[(size_t)r * 64 + f];
        s1 += v;
        s2 += v * v;
    }
    sh1[t] = s1; sh2[t] = s2;
    __syncthreads();
    if (t < 64) {
        float a1 = sh1[t] + sh1[t + 64] + sh1[t + 128] + sh1[t + 192];
        float a2 = sh2[t] + sh2[t + 64] + sh2[t + 128] + sh2[t + 192];
        atomicAdd(&g_sums[t],      (double)a1);
        atomicAdd(&g_sums[64 + t], (double)a2);
    }
}

__global__ void finalize_kernel(const float* __restrict__ gam,
                                const float* __restrict__ bet,
                                double inv_n)
{
    int f = threadIdx.x;
    float mu  = (float)(g_sums[f] * inv_n);
    float var = (float)(g_sums[64 + f] * inv_n) - mu * mu;
    float rs  = rsqrtf(var + 1e-5f);
    float sc  = rs * gam[f];
    g_scale[f] = sc;
    g_shift[f] = bet[f] - mu * sc;
    g_sums[f] = 0.0;
    g_sums[64 + f] = 0.0;
}

__global__ void out_kernel(const float* __restrict__ alpha,
                           float* __restrict__ out, int n)
{
    int idx = blockIdx.x * blockDim.x + threadIdx.x;
    if (idx >= n * 64) return;
    int f = idx & 63;
    float v = g_acc[idx] * g_scale[f] + g_shift[f];
    out[idx] = (v >= 0.f) ? v : alpha[f] * v;
}

// ---------------------------------------------------------------------------
// Launch
// ---------------------------------------------------------------------------
extern "C" void kernel_launch(void* const* d_in, const int* in_sizes, int n_in,
                              void* d_out, int out_size)
{
    const float* x   = (const float*)d_in[0];
    const int*   ei  = (const int*)  d_in[1];
    const int N = in_sizes[0] / 128;
    const int E = in_sizes[1] / 2;
    const int* src = ei;
    const int* dst = ei + E;

    const float* W1  = (const float*)d_in[2];
    const float* G1  = (const float*)d_in[4];
    const float* BE1 = (const float*)d_in[5];
    const float* A1  = (const float*)d_in[6];
    const float* W2  = (const float*)d_in[7];
    const float* G2  = (const float*)d_in[9];
    const float* BE2 = (const float*)d_in[10];
    const float* A2  = (const float*)d_in[11];
    const float* W3  = (const float*)d_in[12];
    const float* G3  = (const float*)d_in[14];
    const float* BE3 = (const float*)d_in[15];
    const float* A3  = (const float*)d_in[16];

    const int smem128 = 384 * (128 + 8) * 2;  // 104448 B
    const int smem64  = 384 * (64 + 8) * 2;   //  55296 B
    cudaFuncSetAttribute((const void*)gemm_mma_kernel<128, false>,
                         cudaFuncAttributeMaxDynamicSharedMemorySize, smem128);
    cudaFuncSetAttribute((const void*)gemm_mma_kernel<64, true>,
                         cudaFuncAttributeMaxDynamicSharedMemorySize, smem64);

    const int gN  = (N + 255) / 256;
    const int gE  = (E + 255) / 256;
    const int gG  = (N + 127) / 128;
    const int gGa = (N * 16 + 255) / 256;
    const int gO  = (N * 64 + 255) / 256;
    const int nb  = (N + 1023) / 1024;
    const double inv_n = 1.0 / (double)N;

    // CSR build (once, reused by all 3 layers)
    deg_init_kernel  <<<gN, 256>>>(N);
    deg_count_kernel <<<gE, 256>>>(dst, E);
    scan_bsum_kernel <<<nb, 256>>>(N);
    scan_tops_kernel <<<1, 32>>>(nb, N, E);
    scan_final_kernel<<<nb, 1024>>>(N);
    fill_adj_kernel  <<<gE, 256>>>(src, dst, E);

    // ---- Layer 1 ----
    gemm_mma_kernel<128, false><<<gG, 512, smem128>>>(x, W1, nullptr, N);
    gather_kernel   <<<gGa, 256>>>(N);
    stats_kernel    <<<gN, 256>>>(N);
    finalize_kernel <<<1, 64>>>(G1, BE1, inv_n);

    // ---- Layer 2 ----
    gemm_mma_kernel<64, true><<<gG, 512, smem64>>>(nullptr, W2, A1, N);
    gather_kernel   <<<gGa, 256>>>(N);
    stats_kernel    <<<gN, 256>>>(N);
    finalize_kernel <<<1, 64>>>(G2, BE2, inv_n);

    // ---- Layer 3 ----
    gemm_mma_kernel<64, true><<<gG, 512, smem64>>>(nullptr, W3, A2, N);
    gather_kernel   <<<gGa, 256>>>(N);
    stats_kernel    <<<gN, 256>>>(N);
    finalize_kernel <<<1, 64>>>(G3, BE3, inv_n);

    out_kernel<<<gO, 256>>>(A3, (float*)d_out, N);
}